// round 2
// baseline (speedup 1.0000x reference)
#include <cuda_runtime.h>
#include <cuda_bf16.h>
#include <cstdint>

// ---------------------------------------------------------------------------
// Problem constants
// ---------------------------------------------------------------------------
#define NPTS   8192
#define CIN    128
#define DDIM   256
#define KNN    16

// Scratch (device globals — no allocation allowed)
__device__ float g_AB[NPTS * 512];      // [i][0:256]=A = x@(W1top-W1bot), [256:512]=B = x@W1bot
__device__ int   g_idx[NPTS * KNN];

// ---------------------------------------------------------------------------
// Kernel 1: exact kNN (top-16, excluding self).
// Branch-free sorted-insertion network -> guaranteed register allocation.
// ---------------------------------------------------------------------------
__global__ void __launch_bounds__(256)
knn_kernel(const float* __restrict__ pos, int* __restrict__ idxout) {
    __shared__ float sx[256], sy[256], sz[256], sq[256];
    const int t = threadIdx.x;
    const int i = blockIdx.x * 256 + t;

    const float xi = pos[i * 3 + 0];
    const float yi = pos[i * 3 + 1];
    const float zi = pos[i * 3 + 2];
    const float sqi = __fadd_rn(__fadd_rn(__fmul_rn(xi, xi), __fmul_rn(yi, yi)),
                                __fmul_rn(zi, zi));

    // sorted ascending: bd[0] smallest ... bd[15] largest
    float bd[KNN];
    int   bi[KNN];
#pragma unroll
    for (int s = 0; s < KNN; s++) { bd[s] = 1e30f; bi[s] = -1; }

    for (int tile = 0; tile < NPTS / 256; tile++) {
        const int j0 = tile * 256;
        __syncthreads();
        {
            const float x = pos[(j0 + t) * 3 + 0];
            const float y = pos[(j0 + t) * 3 + 1];
            const float z = pos[(j0 + t) * 3 + 2];
            sx[t] = x; sy[t] = y; sz[t] = z;
            sq[t] = __fadd_rn(__fadd_rn(__fmul_rn(x, x), __fmul_rn(y, y)),
                              __fmul_rn(z, z));
        }
        __syncthreads();

        for (int jj = 0; jj < 256; jj++) {
            const int j = j0 + jj;
            const float dot = __fadd_rn(__fadd_rn(__fmul_rn(xi, sx[jj]),
                                                  __fmul_rn(yi, sy[jj])),
                                        __fmul_rn(zi, sz[jj]));
            float dist = __fsub_rn(__fadd_rn(sqi, sq[jj]),
                                   __fmul_rn(2.0f, dot));
            if (j == i) continue;
            if (dist < bd[KNN - 1]) {
                // branch-free insertion keeping the list sorted ascending.
                // strict '<' => on ties the earlier (lower-index) entry stays
                // ahead, matching top_k's stable tie-break.
                float d = dist; int id = j;
#pragma unroll
                for (int s = 0; s < KNN; s++) {
                    const bool sw = d < bd[s];
                    const float td = bd[s]; const int ti = bi[s];
                    bd[s] = sw ? d : td;   bi[s] = sw ? id : ti;
                    d     = sw ? td : d;   id    = sw ? ti : id;
                }
            }
        }
    }

#pragma unroll
    for (int s = 0; s < KNN; s++) idxout[i * KNN + s] = bi[s];
}

// ---------------------------------------------------------------------------
// Kernel 2: AB = X(8192x128) @ [W1top - W1bot | W1bot] (128x512)
// 64x64 tile, BK=16, 256 threads, 4x4 per thread. W1 transform fused in B load.
// ---------------------------------------------------------------------------
__global__ void __launch_bounds__(256)
gemm1_kernel(const float* __restrict__ X,
             const float* __restrict__ W1,
             float* __restrict__ AB) {
    __shared__ float As[16][65];   // [k][m], pad kills store conflicts
    __shared__ float Bs[16][64];   // [k][n]

    const int bm = blockIdx.y * 64;
    const int bn = blockIdx.x * 64;
    const int t  = threadIdx.x;
    const int tx = t & 15;
    const int ty = t >> 4;

    float acc[4][4];
#pragma unroll
    for (int a = 0; a < 4; a++)
#pragma unroll
        for (int b = 0; b < 4; b++) acc[a][b] = 0.0f;

    for (int k0 = 0; k0 < CIN; k0 += 16) {
#pragma unroll
        for (int r = 0; r < 4; r++) {
            const int e = t + r * 256;
            const int m = e >> 4, k = e & 15;
            As[k][m] = X[(bm + m) * CIN + k0 + k];
        }
#pragma unroll
        for (int r = 0; r < 4; r++) {
            const int e = t + r * 256;
            const int k = e >> 6, n = e & 63;
            const int gk = k0 + k, gn = bn + n;
            float v;
            if (gn < 256)
                v = W1[gk * 256 + gn] - W1[(gk + 128) * 256 + gn];
            else
                v = W1[(gk + 128) * 256 + (gn - 256)];
            Bs[k][n] = v;
        }
        __syncthreads();

#pragma unroll
        for (int k = 0; k < 16; k++) {
            float a0 = As[k][ty * 4 + 0];
            float a1 = As[k][ty * 4 + 1];
            float a2 = As[k][ty * 4 + 2];
            float a3 = As[k][ty * 4 + 3];
            float b0 = Bs[k][tx * 4 + 0];
            float b1v = Bs[k][tx * 4 + 1];
            float b2v = Bs[k][tx * 4 + 2];
            float b3 = Bs[k][tx * 4 + 3];
            acc[0][0] = fmaf(a0, b0, acc[0][0]); acc[0][1] = fmaf(a0, b1v, acc[0][1]);
            acc[0][2] = fmaf(a0, b2v, acc[0][2]); acc[0][3] = fmaf(a0, b3, acc[0][3]);
            acc[1][0] = fmaf(a1, b0, acc[1][0]); acc[1][1] = fmaf(a1, b1v, acc[1][1]);
            acc[1][2] = fmaf(a1, b2v, acc[1][2]); acc[1][3] = fmaf(a1, b3, acc[1][3]);
            acc[2][0] = fmaf(a2, b0, acc[2][0]); acc[2][1] = fmaf(a2, b1v, acc[2][1]);
            acc[2][2] = fmaf(a2, b2v, acc[2][2]); acc[2][3] = fmaf(a2, b3, acc[2][3]);
            acc[3][0] = fmaf(a3, b0, acc[3][0]); acc[3][1] = fmaf(a3, b1v, acc[3][1]);
            acc[3][2] = fmaf(a3, b2v, acc[3][2]); acc[3][3] = fmaf(a3, b3, acc[3][3]);
        }
        __syncthreads();
    }

#pragma unroll
    for (int ii = 0; ii < 4; ii++)
#pragma unroll
        for (int jj = 0; jj < 4; jj++)
            AB[(bm + ty * 4 + ii) * 512 + bn + tx * 4 + jj] = acc[ii][jj];
}

// ---------------------------------------------------------------------------
// Kernel 3: fused gather + ReLU + (131072x256)@(256x256) + max-over-k + b2
// 2 nodes / block, 256 threads. thread = 8 edges x 4 cols.
// ---------------------------------------------------------------------------
#define EG_NODES 2
#define EG_CHUNK 16
#define H1_STRIDE 20   // 16 edges padded to 20 floats (keeps 16B alignment)

__global__ void __launch_bounds__(256)
edge_gemm_kernel(const float* __restrict__ AB,
                 const int* __restrict__ idx,
                 const float* __restrict__ b1,
                 const float* __restrict__ W2,
                 const float* __restrict__ b2,
                 float* __restrict__ out) {
    extern __shared__ float smem[];
    float* h1s = smem;                                   // [2][256][H1_STRIDE]
    float* w2s = smem + EG_NODES * 256 * H1_STRIDE;      // [CHUNK][256] (reused as red buf)
    __shared__ int idxs[EG_NODES * KNN];

    const int t  = threadIdx.x;
    const int i0 = blockIdx.x * EG_NODES;

    if (t < EG_NODES * KNN) idxs[t] = idx[i0 * KNN + t];
    __syncthreads();

    // ---- Phase A: h1s[n][kk][e] = relu(A[i0+n][kk] + b1[kk] + B[j_e][kk]) ----
    {
        const float b1v = b1[t];
#pragma unroll
        for (int n = 0; n < EG_NODES; n++) {
            const float a = AB[(i0 + n) * 512 + t] + b1v;
            float* hrow = &h1s[(n * 256 + t) * H1_STRIDE];
#pragma unroll
            for (int e = 0; e < KNN; e++) {
                const int j = idxs[n * KNN + e];
                const float v = a + AB[j * 512 + 256 + t];
                hrow[e] = fmaxf(v, 0.0f);
            }
        }
    }
    __syncthreads();

    // ---- Main loop ----
    const int n_t = t >> 7;          // node within block
    const int eg  = (t >> 6) & 1;    // edge group (8 edges each)
    const int cg  = t & 63;          // column group (4 cols each)

    float acc[8][4];
#pragma unroll
    for (int e = 0; e < 8; e++)
#pragma unroll
        for (int c = 0; c < 4; c++) acc[e][c] = 0.0f;

    for (int c0 = 0; c0 < DDIM; c0 += EG_CHUNK) {
#pragma unroll
        for (int r = 0; r < 4; r++) {
            const int e4 = t + r * 256;                  // 1024 float4 = 16x256 floats
            ((float4*)w2s)[e4] = ((const float4*)(W2 + c0 * DDIM))[e4];
        }
        __syncthreads();

#pragma unroll
        for (int kk = 0; kk < EG_CHUNK; kk++) {
            const int k = c0 + kk;
            const float* hp = &h1s[(n_t * 256 + k) * H1_STRIDE + eg * 8];
            const float4 ha = *(const float4*)(hp);      // warp-broadcast
            const float4 hb = *(const float4*)(hp + 4);
            const float4 w  = *(const float4*)&w2s[kk * DDIM + cg * 4];
            // explicit unroll, no local arrays
            acc[0][0] = fmaf(ha.x, w.x, acc[0][0]); acc[0][1] = fmaf(ha.x, w.y, acc[0][1]);
            acc[0][2] = fmaf(ha.x, w.z, acc[0][2]); acc[0][3] = fmaf(ha.x, w.w, acc[0][3]);
            acc[1][0] = fmaf(ha.y, w.x, acc[1][0]); acc[1][1] = fmaf(ha.y, w.y, acc[1][1]);
            acc[1][2] = fmaf(ha.y, w.z, acc[1][2]); acc[1][3] = fmaf(ha.y, w.w, acc[1][3]);
            acc[2][0] = fmaf(ha.z, w.x, acc[2][0]); acc[2][1] = fmaf(ha.z, w.y, acc[2][1]);
            acc[2][2] = fmaf(ha.z, w.z, acc[2][2]); acc[2][3] = fmaf(ha.z, w.w, acc[2][3]);
            acc[3][0] = fmaf(ha.w, w.x, acc[3][0]); acc[3][1] = fmaf(ha.w, w.y, acc[3][1]);
            acc[3][2] = fmaf(ha.w, w.z, acc[3][2]); acc[3][3] = fmaf(ha.w, w.w, acc[3][3]);
            acc[4][0] = fmaf(hb.x, w.x, acc[4][0]); acc[4][1] = fmaf(hb.x, w.y, acc[4][1]);
            acc[4][2] = fmaf(hb.x, w.z, acc[4][2]); acc[4][3] = fmaf(hb.x, w.w, acc[4][3]);
            acc[5][0] = fmaf(hb.y, w.x, acc[5][0]); acc[5][1] = fmaf(hb.y, w.y, acc[5][1]);
            acc[5][2] = fmaf(hb.y, w.z, acc[5][2]); acc[5][3] = fmaf(hb.y, w.w, acc[5][3]);
            acc[6][0] = fmaf(hb.z, w.x, acc[6][0]); acc[6][1] = fmaf(hb.z, w.y, acc[6][1]);
            acc[6][2] = fmaf(hb.z, w.z, acc[6][2]); acc[6][3] = fmaf(hb.z, w.w, acc[6][3]);
            acc[7][0] = fmaf(hb.w, w.x, acc[7][0]); acc[7][1] = fmaf(hb.w, w.y, acc[7][1]);
            acc[7][2] = fmaf(hb.w, w.z, acc[7][2]); acc[7][3] = fmaf(hb.w, w.w, acc[7][3]);
        }
        __syncthreads();
    }

    // ---- Epilogue: max over 8 edges, combine edge-groups, add b2 ----
    float m0 = acc[0][0], m1 = acc[0][1], m2 = acc[0][2], m3 = acc[0][3];
#pragma unroll
    for (int e = 1; e < 8; e++) {
        m0 = fmaxf(m0, acc[e][0]);
        m1 = fmaxf(m1, acc[e][1]);
        m2 = fmaxf(m2, acc[e][2]);
        m3 = fmaxf(m3, acc[e][3]);
    }

    float* red = w2s;  // reuse (last loop iter ended with __syncthreads)
    if (eg == 1) {
        red[n_t * 256 + cg * 4 + 0] = m0;
        red[n_t * 256 + cg * 4 + 1] = m1;
        red[n_t * 256 + cg * 4 + 2] = m2;
        red[n_t * 256 + cg * 4 + 3] = m3;
    }
    __syncthreads();
    if (eg == 0) {
        const int i = i0 + n_t;
        const int col = cg * 4;
        out[i * DDIM + col + 0] = fmaxf(m0, red[n_t * 256 + col + 0]) + b2[col + 0];
        out[i * DDIM + col + 1] = fmaxf(m1, red[n_t * 256 + col + 1]) + b2[col + 1];
        out[i * DDIM + col + 2] = fmaxf(m2, red[n_t * 256 + col + 2]) + b2[col + 2];
        out[i * DDIM + col + 3] = fmaxf(m3, red[n_t * 256 + col + 3]) + b2[col + 3];
    }
}

// ---------------------------------------------------------------------------
// Launch
// ---------------------------------------------------------------------------
extern "C" void kernel_launch(void* const* d_in, const int* in_sizes, int n_in,
                              void* d_out, int out_size) {
    const float* x   = (const float*)d_in[0];   // [8192,128]
    const float* pos = (const float*)d_in[1];   // [8192,3]
    const float* W1  = (const float*)d_in[2];   // [256,256]
    const float* b1  = (const float*)d_in[3];   // [256]
    const float* W2  = (const float*)d_in[4];   // [256,256]
    const float* b2  = (const float*)d_in[5];   // [256]
    float* out = (float*)d_out;                 // [8192,256]
    (void)in_sizes; (void)n_in; (void)out_size;

    // device-global scratch: must go through cudaGetSymbolAddress on the host
    int*   idx_ptr = nullptr;
    float* ab_ptr  = nullptr;
    cudaGetSymbolAddress((void**)&idx_ptr, g_idx);
    cudaGetSymbolAddress((void**)&ab_ptr, g_AB);

    const int smem_bytes = (EG_NODES * 256 * H1_STRIDE + EG_CHUNK * 256) * (int)sizeof(float);
    static bool attr_done = false;
    if (!attr_done) {
        cudaFuncSetAttribute(edge_gemm_kernel,
                             cudaFuncAttributeMaxDynamicSharedMemorySize, smem_bytes);
        attr_done = true;
    }

    knn_kernel<<<NPTS / 256, 256>>>(pos, idx_ptr);
    gemm1_kernel<<<dim3(512 / 64, NPTS / 64), 256>>>(x, W1, ab_ptr);
    edge_gemm_kernel<<<NPTS / EG_NODES, 256, smem_bytes>>>(ab_ptr, idx_ptr, b1, W2, b2, out);
}

// round 3
// speedup vs baseline: 1.8029x; 1.8029x over previous
#include <cuda_runtime.h>
#include <cuda_bf16.h>
#include <cstdint>

// ---------------------------------------------------------------------------
// Problem constants
// ---------------------------------------------------------------------------
#define NPTS   8192
#define CIN    128
#define DDIM   256
#define KNN    16
#define KSEG   16            // kNN split-K segments
#define SEGSZ  (NPTS / KSEG) // 512 points per segment

// Scratch (device globals — no allocation allowed)
__device__ float g_AB[NPTS * 512];      // [i][0:256]=A = x@(W1top-W1bot), [256:512]=B = x@W1bot
__device__ int   g_idx[NPTS * KNN];
__device__ float g_cand_d[NPTS * KSEG * KNN];
__device__ int   g_cand_i[NPTS * KSEG * KNN];

// ---------------------------------------------------------------------------
// Kernel 1a: per-segment top-16. grid=(NPTS/256, KSEG), block=256.
// Each thread: one query i, scans SEGSZ points of segment s from shared mem.
// ---------------------------------------------------------------------------
__global__ void __launch_bounds__(256)
knn_part_kernel(const float* __restrict__ pos,
                float* __restrict__ cand_d, int* __restrict__ cand_i) {
    __shared__ float sx[SEGSZ], sy[SEGSZ], sz[SEGSZ], sq[SEGSZ];
    const int t = threadIdx.x;
    const int i = blockIdx.x * 256 + t;
    const int s = blockIdx.y;
    const int j0 = s * SEGSZ;

    const float xi = pos[i * 3 + 0];
    const float yi = pos[i * 3 + 1];
    const float zi = pos[i * 3 + 2];
    const float sqi = __fadd_rn(__fadd_rn(__fmul_rn(xi, xi), __fmul_rn(yi, yi)),
                                __fmul_rn(zi, zi));

    // load segment points into shared (SEGSZ=512, 256 threads -> 2 each)
#pragma unroll
    for (int r = 0; r < SEGSZ / 256; r++) {
        const int jj = t + r * 256;
        const float x = pos[(j0 + jj) * 3 + 0];
        const float y = pos[(j0 + jj) * 3 + 1];
        const float z = pos[(j0 + jj) * 3 + 2];
        sx[jj] = x; sy[jj] = y; sz[jj] = z;
        sq[jj] = __fadd_rn(__fadd_rn(__fmul_rn(x, x), __fmul_rn(y, y)),
                           __fmul_rn(z, z));
    }
    __syncthreads();

    // sorted ascending top-16 (register-resident, branch-free insertion net)
    float bd[KNN];
    int   bi[KNN];
#pragma unroll
    for (int q = 0; q < KNN; q++) { bd[q] = 1e30f; bi[q] = -1; }

    for (int jj = 0; jj < SEGSZ; jj++) {
        const int j = j0 + jj;
        const float dot = __fadd_rn(__fadd_rn(__fmul_rn(xi, sx[jj]),
                                              __fmul_rn(yi, sy[jj])),
                                    __fmul_rn(zi, sz[jj]));
        const float dist = __fsub_rn(__fadd_rn(sqi, sq[jj]),
                                     __fmul_rn(2.0f, dot));
        if (j == i) continue;
        if (dist < bd[KNN - 1]) {
            float d = dist; int id = j;
#pragma unroll
            for (int q = 0; q < KNN; q++) {
                const bool sw = d < bd[q];
                const float td = bd[q]; const int ti = bi[q];
                bd[q] = sw ? d : td;   bi[q] = sw ? id : ti;
                d     = sw ? td : d;   id    = sw ? ti : id;
            }
        }
    }

    const int base = (i * KSEG + s) * KNN;
#pragma unroll
    for (int q = 0; q < KNN; q++) {
        cand_d[base + q] = bd[q];
        cand_i[base + q] = bi[q];
    }
}

// ---------------------------------------------------------------------------
// Kernel 1b: merge KSEG sorted candidate lists -> final top-16 per query.
// Lists are ascending; early-break per segment once head >= current worst.
// Segment order = ascending j, so strict-< insertion preserves top_k's
// stable lower-index tie-break.
// ---------------------------------------------------------------------------
__global__ void __launch_bounds__(256)
knn_merge_kernel(const float* __restrict__ cand_d, const int* __restrict__ cand_i,
                 int* __restrict__ idxout) {
    const int i = blockIdx.x * 256 + threadIdx.x;

    float bd[KNN];
    int   bi[KNN];
#pragma unroll
    for (int q = 0; q < KNN; q++) { bd[q] = 1e30f; bi[q] = -1; }

    for (int s = 0; s < KSEG; s++) {
        const int base = (i * KSEG + s) * KNN;
#pragma unroll
        for (int e = 0; e < KNN; e++) {
            const float dist = cand_d[base + e];
            if (!(dist < bd[KNN - 1])) break;   // list ascending -> rest also >=
            float d = dist; int id = cand_i[base + e];
#pragma unroll
            for (int q = 0; q < KNN; q++) {
                const bool sw = d < bd[q];
                const float td = bd[q]; const int ti = bi[q];
                bd[q] = sw ? d : td;   bi[q] = sw ? id : ti;
                d     = sw ? td : d;   id    = sw ? ti : id;
            }
        }
    }

#pragma unroll
    for (int q = 0; q < KNN; q++) idxout[i * KNN + q] = bi[q];
}

// ---------------------------------------------------------------------------
// Kernel 2: AB = X(8192x128) @ [W1top - W1bot | W1bot] (128x512)
// ---------------------------------------------------------------------------
__global__ void __launch_bounds__(256)
gemm1_kernel(const float* __restrict__ X,
             const float* __restrict__ W1,
             float* __restrict__ AB) {
    __shared__ float As[16][65];
    __shared__ float Bs[16][64];

    const int bm = blockIdx.y * 64;
    const int bn = blockIdx.x * 64;
    const int t  = threadIdx.x;
    const int tx = t & 15;
    const int ty = t >> 4;

    float acc[4][4];
#pragma unroll
    for (int a = 0; a < 4; a++)
#pragma unroll
        for (int b = 0; b < 4; b++) acc[a][b] = 0.0f;

    for (int k0 = 0; k0 < CIN; k0 += 16) {
#pragma unroll
        for (int r = 0; r < 4; r++) {
            const int e = t + r * 256;
            const int m = e >> 4, k = e & 15;
            As[k][m] = X[(bm + m) * CIN + k0 + k];
        }
#pragma unroll
        for (int r = 0; r < 4; r++) {
            const int e = t + r * 256;
            const int k = e >> 6, n = e & 63;
            const int gk = k0 + k, gn = bn + n;
            float v;
            if (gn < 256)
                v = W1[gk * 256 + gn] - W1[(gk + 128) * 256 + gn];
            else
                v = W1[(gk + 128) * 256 + (gn - 256)];
            Bs[k][n] = v;
        }
        __syncthreads();

#pragma unroll
        for (int k = 0; k < 16; k++) {
            float a0 = As[k][ty * 4 + 0];
            float a1 = As[k][ty * 4 + 1];
            float a2 = As[k][ty * 4 + 2];
            float a3 = As[k][ty * 4 + 3];
            float b0 = Bs[k][tx * 4 + 0];
            float b1v = Bs[k][tx * 4 + 1];
            float b2v = Bs[k][tx * 4 + 2];
            float b3 = Bs[k][tx * 4 + 3];
            acc[0][0] = fmaf(a0, b0, acc[0][0]); acc[0][1] = fmaf(a0, b1v, acc[0][1]);
            acc[0][2] = fmaf(a0, b2v, acc[0][2]); acc[0][3] = fmaf(a0, b3, acc[0][3]);
            acc[1][0] = fmaf(a1, b0, acc[1][0]); acc[1][1] = fmaf(a1, b1v, acc[1][1]);
            acc[1][2] = fmaf(a1, b2v, acc[1][2]); acc[1][3] = fmaf(a1, b3, acc[1][3]);
            acc[2][0] = fmaf(a2, b0, acc[2][0]); acc[2][1] = fmaf(a2, b1v, acc[2][1]);
            acc[2][2] = fmaf(a2, b2v, acc[2][2]); acc[2][3] = fmaf(a2, b3, acc[2][3]);
            acc[3][0] = fmaf(a3, b0, acc[3][0]); acc[3][1] = fmaf(a3, b1v, acc[3][1]);
            acc[3][2] = fmaf(a3, b2v, acc[3][2]); acc[3][3] = fmaf(a3, b3, acc[3][3]);
        }
        __syncthreads();
    }

#pragma unroll
    for (int ii = 0; ii < 4; ii++)
#pragma unroll
        for (int jj = 0; jj < 4; jj++)
            AB[(bm + ty * 4 + ii) * 512 + bn + tx * 4 + jj] = acc[ii][jj];
}

// ---------------------------------------------------------------------------
// Kernel 3: fused gather + ReLU + (131072x256)@(256x256) + max-over-k + b2
// ---------------------------------------------------------------------------
#define EG_NODES 2
#define EG_CHUNK 16
#define H1_STRIDE 20

__global__ void __launch_bounds__(256)
edge_gemm_kernel(const float* __restrict__ AB,
                 const int* __restrict__ idx,
                 const float* __restrict__ b1,
                 const float* __restrict__ W2,
                 const float* __restrict__ b2,
                 float* __restrict__ out) {
    extern __shared__ float smem[];
    float* h1s = smem;                                   // [2][256][H1_STRIDE]
    float* w2s = smem + EG_NODES * 256 * H1_STRIDE;      // [CHUNK][256]
    __shared__ int idxs[EG_NODES * KNN];

    const int t  = threadIdx.x;
    const int i0 = blockIdx.x * EG_NODES;

    if (t < EG_NODES * KNN) idxs[t] = idx[i0 * KNN + t];
    __syncthreads();

    {
        const float b1v = b1[t];
#pragma unroll
        for (int n = 0; n < EG_NODES; n++) {
            const float a = AB[(i0 + n) * 512 + t] + b1v;
            float* hrow = &h1s[(n * 256 + t) * H1_STRIDE];
#pragma unroll
            for (int e = 0; e < KNN; e++) {
                const int j = idxs[n * KNN + e];
                const float v = a + AB[j * 512 + 256 + t];
                hrow[e] = fmaxf(v, 0.0f);
            }
        }
    }
    __syncthreads();

    const int n_t = t >> 7;
    const int eg  = (t >> 6) & 1;
    const int cg  = t & 63;

    float acc[8][4];
#pragma unroll
    for (int e = 0; e < 8; e++)
#pragma unroll
        for (int c = 0; c < 4; c++) acc[e][c] = 0.0f;

    for (int c0 = 0; c0 < DDIM; c0 += EG_CHUNK) {
#pragma unroll
        for (int r = 0; r < 4; r++) {
            const int e4 = t + r * 256;
            ((float4*)w2s)[e4] = ((const float4*)(W2 + c0 * DDIM))[e4];
        }
        __syncthreads();

#pragma unroll
        for (int kk = 0; kk < EG_CHUNK; kk++) {
            const int k = c0 + kk;
            const float* hp = &h1s[(n_t * 256 + k) * H1_STRIDE + eg * 8];
            const float4 ha = *(const float4*)(hp);
            const float4 hb = *(const float4*)(hp + 4);
            const float4 w  = *(const float4*)&w2s[kk * DDIM + cg * 4];
            acc[0][0] = fmaf(ha.x, w.x, acc[0][0]); acc[0][1] = fmaf(ha.x, w.y, acc[0][1]);
            acc[0][2] = fmaf(ha.x, w.z, acc[0][2]); acc[0][3] = fmaf(ha.x, w.w, acc[0][3]);
            acc[1][0] = fmaf(ha.y, w.x, acc[1][0]); acc[1][1] = fmaf(ha.y, w.y, acc[1][1]);
            acc[1][2] = fmaf(ha.y, w.z, acc[1][2]); acc[1][3] = fmaf(ha.y, w.w, acc[1][3]);
            acc[2][0] = fmaf(ha.z, w.x, acc[2][0]); acc[2][1] = fmaf(ha.z, w.y, acc[2][1]);
            acc[2][2] = fmaf(ha.z, w.z, acc[2][2]); acc[2][3] = fmaf(ha.z, w.w, acc[2][3]);
            acc[3][0] = fmaf(ha.w, w.x, acc[3][0]); acc[3][1] = fmaf(ha.w, w.y, acc[3][1]);
            acc[3][2] = fmaf(ha.w, w.z, acc[3][2]); acc[3][3] = fmaf(ha.w, w.w, acc[3][3]);
            acc[4][0] = fmaf(hb.x, w.x, acc[4][0]); acc[4][1] = fmaf(hb.x, w.y, acc[4][1]);
            acc[4][2] = fmaf(hb.x, w.z, acc[4][2]); acc[4][3] = fmaf(hb.x, w.w, acc[4][3]);
            acc[5][0] = fmaf(hb.y, w.x, acc[5][0]); acc[5][1] = fmaf(hb.y, w.y, acc[5][1]);
            acc[5][2] = fmaf(hb.y, w.z, acc[5][2]); acc[5][3] = fmaf(hb.y, w.w, acc[5][3]);
            acc[6][0] = fmaf(hb.z, w.x, acc[6][0]); acc[6][1] = fmaf(hb.z, w.y, acc[6][1]);
            acc[6][2] = fmaf(hb.z, w.z, acc[6][2]); acc[6][3] = fmaf(hb.z, w.w, acc[6][3]);
            acc[7][0] = fmaf(hb.w, w.x, acc[7][0]); acc[7][1] = fmaf(hb.w, w.y, acc[7][1]);
            acc[7][2] = fmaf(hb.w, w.z, acc[7][2]); acc[7][3] = fmaf(hb.w, w.w, acc[7][3]);
        }
        __syncthreads();
    }

    float m0 = acc[0][0], m1 = acc[0][1], m2 = acc[0][2], m3 = acc[0][3];
#pragma unroll
    for (int e = 1; e < 8; e++) {
        m0 = fmaxf(m0, acc[e][0]);
        m1 = fmaxf(m1, acc[e][1]);
        m2 = fmaxf(m2, acc[e][2]);
        m3 = fmaxf(m3, acc[e][3]);
    }

    float* red = w2s;
    if (eg == 1) {
        red[n_t * 256 + cg * 4 + 0] = m0;
        red[n_t * 256 + cg * 4 + 1] = m1;
        red[n_t * 256 + cg * 4 + 2] = m2;
        red[n_t * 256 + cg * 4 + 3] = m3;
    }
    __syncthreads();
    if (eg == 0) {
        const int i = i0 + n_t;
        const int col = cg * 4;
        out[i * DDIM + col + 0] = fmaxf(m0, red[n_t * 256 + col + 0]) + b2[col + 0];
        out[i * DDIM + col + 1] = fmaxf(m1, red[n_t * 256 + col + 1]) + b2[col + 1];
        out[i * DDIM + col + 2] = fmaxf(m2, red[n_t * 256 + col + 2]) + b2[col + 2];
        out[i * DDIM + col + 3] = fmaxf(m3, red[n_t * 256 + col + 3]) + b2[col + 3];
    }
}

// ---------------------------------------------------------------------------
// Launch
// ---------------------------------------------------------------------------
extern "C" void kernel_launch(void* const* d_in, const int* in_sizes, int n_in,
                              void* d_out, int out_size) {
    const float* x   = (const float*)d_in[0];   // [8192,128]
    const float* pos = (const float*)d_in[1];   // [8192,3]
    const float* W1  = (const float*)d_in[2];   // [256,256]
    const float* b1  = (const float*)d_in[3];   // [256]
    const float* W2  = (const float*)d_in[4];   // [256,256]
    const float* b2  = (const float*)d_in[5];   // [256]
    float* out = (float*)d_out;                 // [8192,256]
    (void)in_sizes; (void)n_in; (void)out_size;

    int*   idx_ptr = nullptr;
    float* ab_ptr  = nullptr;
    float* cd_ptr  = nullptr;
    int*   ci_ptr  = nullptr;
    cudaGetSymbolAddress((void**)&idx_ptr, g_idx);
    cudaGetSymbolAddress((void**)&ab_ptr, g_AB);
    cudaGetSymbolAddress((void**)&cd_ptr, g_cand_d);
    cudaGetSymbolAddress((void**)&ci_ptr, g_cand_i);

    const int smem_bytes = (EG_NODES * 256 * H1_STRIDE + EG_CHUNK * 256) * (int)sizeof(float);
    static bool attr_done = false;
    if (!attr_done) {
        cudaFuncSetAttribute(edge_gemm_kernel,
                             cudaFuncAttributeMaxDynamicSharedMemorySize, smem_bytes);
        attr_done = true;
    }

    knn_part_kernel<<<dim3(NPTS / 256, KSEG), 256>>>(pos, cd_ptr, ci_ptr);
    knn_merge_kernel<<<NPTS / 256, 256>>>(cd_ptr, ci_ptr, idx_ptr);
    gemm1_kernel<<<dim3(512 / 64, NPTS / 64), 256>>>(x, W1, ab_ptr);
    edge_gemm_kernel<<<NPTS / EG_NODES, 256, smem_bytes>>>(ab_ptr, idx_ptr, b1, W2, b2, out);
}

// round 5
// speedup vs baseline: 2.4133x; 1.3386x over previous
#include <cuda_runtime.h>
#include <cuda_bf16.h>
#include <cstdint>

// ---------------------------------------------------------------------------
// Problem constants
// ---------------------------------------------------------------------------
#define NPTS   8192
#define CIN    128
#define DDIM   256
#define KNN    16
#define KSEG   16
#define SEGSZ  (NPTS / KSEG)

#define NODES_PB 8            // nodes per edge-MMA block (M = 8*16 = 128)
#define EM_THREADS 512        // 16 warps: 4 (m) x 4 (n)

// Scratch (device globals — no allocation allowed)
__device__ float g_AB[NPTS * 512];          // [i][0:256]=A=x@(W1t-W1b)+b1, [256:512]=B=x@W1b
__device__ int   g_idx[NPTS * KNN];
__device__ float g_cand_d[NPTS * KSEG * KNN];
__device__ int   g_cand_i[NPTS * KSEG * KNN];
// W2 split into bf16 hi/lo, row-major [k][n] images (u32 = 2 packed bf16 along n)
__device__ uint32_t g_W2hi32[32768];        // 128 KB
__device__ uint32_t g_W2lo32[32768];        // 128 KB

// ---------------------------------------------------------------------------
// PTX helpers: ldmatrix + mma.sync (sm_80-level ISA; works on plain sm_100)
// ---------------------------------------------------------------------------
__device__ __forceinline__ uint32_t smem_u32(const void* p) {
    uint32_t a;
    asm("{ .reg .u64 t; cvta.to.shared.u64 t, %1; cvt.u32.u64 %0, t; }"
        : "=r"(a) : "l"(p));
    return a;
}
__device__ __forceinline__ void ldsm_x4(uint32_t& r0, uint32_t& r1,
                                        uint32_t& r2, uint32_t& r3, uint32_t addr) {
    asm volatile("ldmatrix.sync.aligned.m8n8.x4.shared.b16 {%0,%1,%2,%3}, [%4];"
                 : "=r"(r0), "=r"(r1), "=r"(r2), "=r"(r3) : "r"(addr));
}
__device__ __forceinline__ void ldsm_x4_t(uint32_t& r0, uint32_t& r1,
                                          uint32_t& r2, uint32_t& r3, uint32_t addr) {
    asm volatile("ldmatrix.sync.aligned.m8n8.x4.trans.shared.b16 {%0,%1,%2,%3}, [%4];"
                 : "=r"(r0), "=r"(r1), "=r"(r2), "=r"(r3) : "r"(addr));
}
__device__ __forceinline__ void mma_bf16(float& d0, float& d1, float& d2, float& d3,
                                         uint32_t a0, uint32_t a1, uint32_t a2, uint32_t a3,
                                         uint32_t b0, uint32_t b1) {
    asm volatile("mma.sync.aligned.m16n8k16.row.col.f32.bf16.bf16.f32 "
                 "{%0,%1,%2,%3}, {%4,%5,%6,%7}, {%8,%9}, {%0,%1,%2,%3};"
                 : "+f"(d0), "+f"(d1), "+f"(d2), "+f"(d3)
                 : "r"(a0), "r"(a1), "r"(a2), "r"(a3), "r"(b0), "r"(b1));
}
__device__ __forceinline__ uint32_t pack_hi2(float v0, float v1) {
    return ((uint32_t)__bfloat16_as_ushort(__float2bfloat16_rn(v1)) << 16) |
           (uint32_t)__bfloat16_as_ushort(__float2bfloat16_rn(v0));
}

// ---------------------------------------------------------------------------
// Kernel 1a: per-segment top-16 (arithmetic sequence matches reference)
// ---------------------------------------------------------------------------
__global__ void __launch_bounds__(256)
knn_part_kernel(const float* __restrict__ pos,
                float* __restrict__ cand_d, int* __restrict__ cand_i) {
    __shared__ float4 s4[SEGSZ];
    const int t = threadIdx.x;
    const int i = blockIdx.x * 256 + t;
    const int s = blockIdx.y;
    const int j0 = s * SEGSZ;

    const float xi = pos[i * 3 + 0];
    const float yi = pos[i * 3 + 1];
    const float zi = pos[i * 3 + 2];
    const float sqi = __fadd_rn(__fadd_rn(__fmul_rn(xi, xi), __fmul_rn(yi, yi)),
                                __fmul_rn(zi, zi));

#pragma unroll
    for (int r = 0; r < SEGSZ / 256; r++) {
        const int jj = t + r * 256;
        const float x = pos[(j0 + jj) * 3 + 0];
        const float y = pos[(j0 + jj) * 3 + 1];
        const float z = pos[(j0 + jj) * 3 + 2];
        const float sq = __fadd_rn(__fadd_rn(__fmul_rn(x, x), __fmul_rn(y, y)),
                                   __fmul_rn(z, z));
        s4[jj] = make_float4(x, y, z, sq);
    }
    __syncthreads();

    float bd[KNN];
    int   bi[KNN];
#pragma unroll
    for (int q = 0; q < KNN; q++) { bd[q] = 1e30f; bi[q] = -1; }

#pragma unroll 4
    for (int jj = 0; jj < SEGSZ; jj++) {
        const int j = j0 + jj;
        const float4 p = s4[jj];
        const float dot = __fadd_rn(__fadd_rn(__fmul_rn(xi, p.x),
                                              __fmul_rn(yi, p.y)),
                                    __fmul_rn(zi, p.z));
        const float dist = __fsub_rn(__fadd_rn(sqi, p.w),
                                     __fmul_rn(2.0f, dot));
        if (j == i) continue;
        if (dist < bd[KNN - 1]) {
            float d = dist; int id = j;
#pragma unroll
            for (int q = 0; q < KNN; q++) {
                const bool sw = d < bd[q];
                const float td = bd[q]; const int ti = bi[q];
                bd[q] = sw ? d : td;   bi[q] = sw ? id : ti;
                d     = sw ? td : d;   id    = sw ? ti : id;
            }
        }
    }

    const int base = (i * KSEG + s) * KNN;
#pragma unroll
    for (int q = 0; q < KNN; q++) {
        cand_d[base + q] = bd[q];
        cand_i[base + q] = bi[q];
    }
}

// ---------------------------------------------------------------------------
// Kernel 1b: merge sorted candidate lists
// ---------------------------------------------------------------------------
__global__ void __launch_bounds__(256)
knn_merge_kernel(const float* __restrict__ cand_d, const int* __restrict__ cand_i,
                 int* __restrict__ idxout) {
    const int i = blockIdx.x * 256 + threadIdx.x;

    float bd[KNN];
    int   bi[KNN];
#pragma unroll
    for (int q = 0; q < KNN; q++) { bd[q] = 1e30f; bi[q] = -1; }

    for (int s = 0; s < KSEG; s++) {
        const int base = (i * KSEG + s) * KNN;
#pragma unroll
        for (int e = 0; e < KNN; e++) {
            const float dist = cand_d[base + e];
            if (!(dist < bd[KNN - 1])) break;
            float d = dist; int id = cand_i[base + e];
#pragma unroll
            for (int q = 0; q < KNN; q++) {
                const bool sw = d < bd[q];
                const float td = bd[q]; const int ti = bi[q];
                bd[q] = sw ? d : td;   bi[q] = sw ? id : ti;
                d     = sw ? td : d;   id    = sw ? ti : id;
            }
        }
    }

#pragma unroll
    for (int q = 0; q < KNN; q++) idxout[i * KNN + q] = bi[q];
}

// ---------------------------------------------------------------------------
// Kernel 2: AB = X @ [W1top - W1bot | W1bot], b1 folded into A columns
// ---------------------------------------------------------------------------
__global__ void __launch_bounds__(256)
gemm1_kernel(const float* __restrict__ X,
             const float* __restrict__ W1,
             const float* __restrict__ b1,
             float* __restrict__ AB) {
    __shared__ float As[16][65];
    __shared__ float Bs[16][64];

    const int bm = blockIdx.y * 64;
    const int bn = blockIdx.x * 64;
    const int t  = threadIdx.x;
    const int tx = t & 15;
    const int ty = t >> 4;

    float acc[4][4];
#pragma unroll
    for (int a = 0; a < 4; a++)
#pragma unroll
        for (int b = 0; b < 4; b++) acc[a][b] = 0.0f;

    for (int k0 = 0; k0 < CIN; k0 += 16) {
#pragma unroll
        for (int r = 0; r < 4; r++) {
            const int e = t + r * 256;
            const int m = e >> 4, k = e & 15;
            As[k][m] = X[(bm + m) * CIN + k0 + k];
        }
#pragma unroll
        for (int r = 0; r < 4; r++) {
            const int e = t + r * 256;
            const int k = e >> 6, n = e & 63;
            const int gk = k0 + k, gn = bn + n;
            float v;
            if (gn < 256)
                v = W1[gk * 256 + gn] - W1[(gk + 128) * 256 + gn];
            else
                v = W1[(gk + 128) * 256 + (gn - 256)];
            Bs[k][n] = v;
        }
        __syncthreads();

#pragma unroll
        for (int k = 0; k < 16; k++) {
            float a0 = As[k][ty * 4 + 0];
            float a1 = As[k][ty * 4 + 1];
            float a2 = As[k][ty * 4 + 2];
            float a3 = As[k][ty * 4 + 3];
            float b0 = Bs[k][tx * 4 + 0];
            float c1 = Bs[k][tx * 4 + 1];
            float c2 = Bs[k][tx * 4 + 2];
            float b3 = Bs[k][tx * 4 + 3];
            acc[0][0] = fmaf(a0, b0, acc[0][0]); acc[0][1] = fmaf(a0, c1, acc[0][1]);
            acc[0][2] = fmaf(a0, c2, acc[0][2]); acc[0][3] = fmaf(a0, b3, acc[0][3]);
            acc[1][0] = fmaf(a1, b0, acc[1][0]); acc[1][1] = fmaf(a1, c1, acc[1][1]);
            acc[1][2] = fmaf(a1, c2, acc[1][2]); acc[1][3] = fmaf(a1, b3, acc[1][3]);
            acc[2][0] = fmaf(a2, b0, acc[2][0]); acc[2][1] = fmaf(a2, c1, acc[2][1]);
            acc[2][2] = fmaf(a2, c2, acc[2][2]); acc[2][3] = fmaf(a2, b3, acc[2][3]);
            acc[3][0] = fmaf(a3, b0, acc[3][0]); acc[3][1] = fmaf(a3, c1, acc[3][1]);
            acc[3][2] = fmaf(a3, c2, acc[3][2]); acc[3][3] = fmaf(a3, b3, acc[3][3]);
        }
        __syncthreads();
    }

#pragma unroll
    for (int ii = 0; ii < 4; ii++)
#pragma unroll
        for (int jj = 0; jj < 4; jj++) {
            const int gn = bn + tx * 4 + jj;
            const float bias = (gn < 256) ? b1[gn] : 0.0f;
            AB[(bm + ty * 4 + ii) * 512 + gn] = acc[ii][jj] + bias;
        }
}

// ---------------------------------------------------------------------------
// Kernel 2b: split W2 into bf16 hi/lo row-major [k][n] images
// ---------------------------------------------------------------------------
__global__ void __launch_bounds__(256)
w2split_kernel(const float* __restrict__ W2) {
    const int id = blockIdx.x * 256 + threadIdx.x;   // 16384 threads, 4 floats each
    const float4 v = ((const float4*)W2)[id];

    const __nv_bfloat16 h0 = __float2bfloat16_rn(v.x);
    const __nv_bfloat16 h1 = __float2bfloat16_rn(v.y);
    const __nv_bfloat16 h2 = __float2bfloat16_rn(v.z);
    const __nv_bfloat16 h3 = __float2bfloat16_rn(v.w);

    g_W2hi32[id * 2 + 0] = ((uint32_t)__bfloat16_as_ushort(h1) << 16) |
                           (uint32_t)__bfloat16_as_ushort(h0);
    g_W2hi32[id * 2 + 1] = ((uint32_t)__bfloat16_as_ushort(h3) << 16) |
                           (uint32_t)__bfloat16_as_ushort(h2);
    g_W2lo32[id * 2 + 0] = pack_hi2(v.x - __bfloat162float(h0),
                                    v.y - __bfloat162float(h1));
    g_W2lo32[id * 2 + 1] = pack_hi2(v.z - __bfloat162float(h2),
                                    v.w - __bfloat162float(h3));
}

// ---------------------------------------------------------------------------
// Kernel 3: mma.sync bf16 edge GEMM. Block = 8 nodes (M=128), N=256, K=256.
// 16 warps: warp tile m32 (2 nodes) x n64. 3-term split: AhiBhi+AhiBlo+AloBhi.
// h1 hi/lo staged in smem (XOR-swizzled 16B chunks); W2 hi/lo streamed in
// k=64 chunks. Epilogue: warp-local max over each node's 16 edge rows + b2.
// ---------------------------------------------------------------------------
#define SA_HI 0
#define SA_LO 65536
#define SB_HI 131072
#define SB_LO 163840
#define SM_TOTAL 196608

__global__ void __launch_bounds__(EM_THREADS, 1)
edge_mma_kernel(const float* __restrict__ AB,
                const int* __restrict__ idx,
                const float* __restrict__ b2,
                float* __restrict__ out) {
    extern __shared__ char smem[];
    const uint32_t sbase = smem_u32(smem);
    __shared__ int idxs[128];

    const int t    = threadIdx.x;
    const int lane = t & 31;
    const int wid  = t >> 5;
    const int wm   = wid & 3;        // m-warp: rows 32*wm (2 nodes)
    const int wn   = wid >> 2;       // n-warp: cols 64*wn
    const int i0   = blockIdx.x * NODES_PB;

    if (t < 128) idxs[t] = idx[i0 * KNN + t];
    __syncthreads();

    // ---- Phase A: gather + relu + bf16 split -> smem (rows = edges) ----
    {
        const int r = t >> 2;                 // edge row 0..127
        const int q = t & 3;                  // 64-col quarter
        const int j = idxs[r];
        const float4* arow = (const float4*)(AB + (size_t)(i0 + (r >> 4)) * 512) + q * 16;
        const float4* brow = (const float4*)(AB + (size_t)j * 512 + 256) + q * 16;
        const int sw_r = r & 7;
        char* smem_c = smem;
#pragma unroll
        for (int w = 0; w < 8; w++) {
            const float4 a0 = arow[w * 2 + 0];
            const float4 a1 = arow[w * 2 + 1];
            const float4 e0 = brow[w * 2 + 0];
            const float4 e1 = brow[w * 2 + 1];
            const float v0 = fmaxf(a0.x + e0.x, 0.0f);
            const float v1 = fmaxf(a0.y + e0.y, 0.0f);
            const float v2 = fmaxf(a0.z + e0.z, 0.0f);
            const float v3 = fmaxf(a0.w + e0.w, 0.0f);
            const float v4 = fmaxf(a1.x + e1.x, 0.0f);
            const float v5 = fmaxf(a1.y + e1.y, 0.0f);
            const float v6 = fmaxf(a1.z + e1.z, 0.0f);
            const float v7 = fmaxf(a1.w + e1.w, 0.0f);
            const __nv_bfloat16 h0 = __float2bfloat16_rn(v0);
            const __nv_bfloat16 h1 = __float2bfloat16_rn(v1);
            const __nv_bfloat16 h2 = __float2bfloat16_rn(v2);
            const __nv_bfloat16 h3 = __float2bfloat16_rn(v3);
            const __nv_bfloat16 h4 = __float2bfloat16_rn(v4);
            const __nv_bfloat16 h5 = __float2bfloat16_rn(v5);
            const __nv_bfloat16 h6 = __float2bfloat16_rn(v6);
            const __nv_bfloat16 h7 = __float2bfloat16_rn(v7);
            uint4 H, L;
            H.x = ((uint32_t)__bfloat16_as_ushort(h1) << 16) | __bfloat16_as_ushort(h0);
            H.y = ((uint32_t)__bfloat16_as_ushort(h3) << 16) | __bfloat16_as_ushort(h2);
            H.z = ((uint32_t)__bfloat16_as_ushort(h5) << 16) | __bfloat16_as_ushort(h4);
            H.w = ((uint32_t)__bfloat16_as_ushort(h7) << 16) | __bfloat16_as_ushort(h6);
            L.x = pack_hi2(v0 - __bfloat162float(h0), v1 - __bfloat162float(h1));
            L.y = pack_hi2(v2 - __bfloat162float(h2), v3 - __bfloat162float(h3));
            L.z = pack_hi2(v4 - __bfloat162float(h4), v5 - __bfloat162float(h5));
            L.w = pack_hi2(v6 - __bfloat162float(h6), v7 - __bfloat162float(h7));
            const int c = (q * 8 + w) ^ sw_r;
            *(uint4*)(smem_c + SA_HI + r * 512 + c * 16) = H;
            *(uint4*)(smem_c + SA_LO + r * 512 + c * 16) = L;
        }
    }
    __syncthreads();

    // ---- Main loop: K=256 in 4 chunks of 64 ----
    float D[2][8][4];
#pragma unroll
    for (int mt = 0; mt < 2; mt++)
#pragma unroll
        for (int f = 0; f < 8; f++)
#pragma unroll
            for (int c = 0; c < 4; c++) D[mt][f][c] = 0.0f;

    const int a_row  = wm * 32 + (lane & 15);
    const int a_swz  = a_row & 7;
    const uint32_t a_base_hi = sbase + SA_HI + a_row * 512;
    const uint32_t a_base_lo = sbase + SA_LO + a_row * 512;
    const int b_krow = lane & 15;                 // k row within k16 tile
    const int b_cbase = wn * 8 + (lane >> 4);     // 16B chunk base along n

    for (int kc = 0; kc < 4; kc++) {
        // copy W2 hi/lo k-chunk [64 rows][256 cols] into smem (swizzled)
        {
            char* smem_c = smem;
#pragma unroll
            for (int ii = 0; ii < 4; ii++) {
                const int e = t + ii * EM_THREADS;        // 0..2047
                const int row = e >> 5, c = e & 31;
                const int src = (kc * 64 + row) * 32 + c; // uint4 index
                const int dst = row * 512 + ((c ^ (row & 7)) * 16);
                *(uint4*)(smem_c + SB_HI + dst) = ((const uint4*)g_W2hi32)[src];
                *(uint4*)(smem_c + SB_LO + dst) = ((const uint4*)g_W2lo32)[src];
            }
        }
        __syncthreads();

#pragma unroll
        for (int kt = 0; kt < 4; kt++) {
            const int kg = kc * 4 + kt;           // global k16 index 0..15
            // A fragments (hi, lo) for both m16 tiles
            uint32_t ah[2][4], al[2][4];
#pragma unroll
            for (int mt = 0; mt < 2; mt++) {
                const uint32_t roff = mt * 16 * 512;
                const uint32_t c = (uint32_t)((kg * 2 + (lane >> 4)) ^ a_swz) * 16;
                ldsm_x4(ah[mt][0], ah[mt][1], ah[mt][2], ah[mt][3], a_base_hi + roff + c);
                ldsm_x4(al[mt][0], al[mt][1], al[mt][2], al[mt][3], a_base_lo + roff + c);
            }
#pragma unroll
            for (int g = 0; g < 4; g++) {
                const int krow = kt * 16 + b_krow;
                const uint32_t c = (uint32_t)((b_cbase + g * 2) ^ (krow & 7)) * 16;
                const uint32_t baddr = krow * 512 + c;
                uint32_t bh0, bh1, bh2, bh3, bl0, bl1, bl2, bl3;
                ldsm_x4_t(bh0, bh1, bh2, bh3, sbase + SB_HI + baddr);
                ldsm_x4_t(bl0, bl1, bl2, bl3, sbase + SB_LO + baddr);
#pragma unroll
                for (int mt = 0; mt < 2; mt++) {
                    float* d0 = D[mt][g * 2 + 0];
                    float* d1 = D[mt][g * 2 + 1];
                    mma_bf16(d0[0], d0[1], d0[2], d0[3],
                             ah[mt][0], ah[mt][1], ah[mt][2], ah[mt][3], bh0, bh1);
                    mma_bf16(d0[0], d0[1], d0[2], d0[3],
                             ah[mt][0], ah[mt][1], ah[mt][2], ah[mt][3], bl0, bl1);
                    mma_bf16(d0[0], d0[1], d0[2], d0[3],
                             al[mt][0], al[mt][1], al[mt][2], al[mt][3], bh0, bh1);
                    mma_bf16(d1[0], d1[1], d1[2], d1[3],
                             ah[mt][0], ah[mt][1], ah[mt][2], ah[mt][3], bh2, bh3);
                    mma_bf16(d1[0], d1[1], d1[2], d1[3],
                             ah[mt][0], ah[mt][1], ah[mt][2], ah[mt][3], bl2, bl3);
                    mma_bf16(d1[0], d1[1], d1[2], d1[3],
                             al[mt][0], al[mt][1], al[mt][2], al[mt][3], bh2, bh3);
                }
            }
        }
        __syncthreads();
    }

    // ---- Epilogue: max over each node's 16 rows (warp-local) + b2 ----
#pragma unroll
    for (int mt = 0; mt < 2; mt++) {
        const int node = i0 + wm * 2 + mt;
#pragma unroll
        for (int f = 0; f < 8; f++) {
            float m0 = fmaxf(D[mt][f][0], D[mt][f][2]);   // rows r, r+8
            float m1 = fmaxf(D[mt][f][1], D[mt][f][3]);
            m0 = fmaxf(m0, __shfl_xor_sync(0xffffffffu, m0, 4));
            m1 = fmaxf(m1, __shfl_xor_sync(0xffffffffu, m1, 4));
            m0 = fmaxf(m0, __shfl_xor_sync(0xffffffffu, m0, 8));
            m1 = fmaxf(m1, __shfl_xor_sync(0xffffffffu, m1, 8));
            m0 = fmaxf(m0, __shfl_xor_sync(0xffffffffu, m0, 16));
            m1 = fmaxf(m1, __shfl_xor_sync(0xffffffffu, m1, 16));
            if ((lane >> 2) == 0) {
                const int col = wn * 64 + f * 8 + 2 * (lane & 3);
                float2 o;
                o.x = m0 + b2[col];
                o.y = m1 + b2[col + 1];
                *(float2*)(out + (size_t)node * DDIM + col) = o;
            }
        }
    }
}

// ---------------------------------------------------------------------------
// Launch
// ---------------------------------------------------------------------------
extern "C" void kernel_launch(void* const* d_in, const int* in_sizes, int n_in,
                              void* d_out, int out_size) {
    const float* x   = (const float*)d_in[0];
    const float* pos = (const float*)d_in[1];
    const float* W1  = (const float*)d_in[2];
    const float* b1  = (const float*)d_in[3];
    const float* W2  = (const float*)d_in[4];
    const float* b2  = (const float*)d_in[5];
    float* out = (float*)d_out;
    (void)in_sizes; (void)n_in; (void)out_size;

    int*   idx_ptr = nullptr;
    float* ab_ptr  = nullptr;
    float* cd_ptr  = nullptr;
    int*   ci_ptr  = nullptr;
    cudaGetSymbolAddress((void**)&idx_ptr, g_idx);
    cudaGetSymbolAddress((void**)&ab_ptr, g_AB);
    cudaGetSymbolAddress((void**)&cd_ptr, g_cand_d);
    cudaGetSymbolAddress((void**)&ci_ptr, g_cand_i);

    static bool attr_done = false;
    if (!attr_done) {
        cudaFuncSetAttribute(edge_mma_kernel,
                             cudaFuncAttributeMaxDynamicSharedMemorySize, SM_TOTAL);
        attr_done = true;
    }

    knn_part_kernel<<<dim3(NPTS / 256, KSEG), 256>>>(pos, cd_ptr, ci_ptr);
    knn_merge_kernel<<<NPTS / 256, 256>>>(cd_ptr, ci_ptr, idx_ptr);
    gemm1_kernel<<<dim3(512 / 64, NPTS / 64), 256>>>(x, W1, b1, ab_ptr);
    w2split_kernel<<<64, 256>>>(W2);
    edge_mma_kernel<<<NPTS / NODES_PB, EM_THREADS, SM_TOTAL>>>(ab_ptr, idx_ptr, b2, out);
}